// round 1
// baseline (speedup 1.0000x reference)
#include <cuda_runtime.h>

#define NN 50000
#define DD 128
#define HHEADS 4
#define CCH 32
#define EE 600000

// Scratch (device globals: no allocation allowed)
__device__ __align__(256) float g_xt[(size_t)NN * DD];
__device__ __align__(256) float g_h[(size_t)NN * DD];
__device__ __align__(256) float g_asrc[NN * HHEADS];
__device__ __align__(256) float g_adst[NN * HHEADS];
__device__ __align__(256) float g_asum[NN * HHEADS];
__device__ __align__(256) float g_agg[(size_t)NN * DD];

__device__ __forceinline__ void red_add_f4(float* p, float4 v) {
    asm volatile("red.global.add.v4.f32 [%0], {%1,%2,%3,%4};"
                 :: "l"(p), "f"(v.x), "f"(v.y), "f"(v.z), "f"(v.w) : "memory");
}

// ---------------------------------------------------------------------------
// K2: fused LayerNorm1 + GEMM (xt = LN(x); h = xt @ W). Tile 128 rows.
// Smem: As[k][row] transposed (128x132 padded), Ws[k][col] (128x128).
// Thread (tx,ty) in 16x16 grid computes rows {4ty+i, 64+4ty+i} x cols {4tx+j, 64+4tx+j}.
// ---------------------------------------------------------------------------
extern __shared__ float smem_dyn[];

__global__ __launch_bounds__(256, 1)
void k_ln_gemm(const float* __restrict__ x, const float* __restrict__ Wg,
               const float* __restrict__ g1, const float* __restrict__ b1) {
    float* As = smem_dyn;              // 128 * 132
    float* Ws = smem_dyn + 128 * 132;  // 128 * 128
    const int t = threadIdx.x;
    const int lane = t & 31;
    const int wid = t >> 5;
    const int row0 = blockIdx.x * 128;

    // Load W (row-major [k][col]) straight into smem
    {
        const float4* W4 = (const float4*)Wg;
        float4* Ws4 = (float4*)Ws;
#pragma unroll
        for (int i = 0; i < 16; i++) Ws4[t + 256 * i] = W4[t + 256 * i];
    }

    // LayerNorm phase: warp `wid` handles rows wid + 8*i (16 rows/warp)
    const float4 gv = __ldg(((const float4*)g1) + lane);
    const float4 bv = __ldg(((const float4*)b1) + lane);
#pragma unroll 1
    for (int i = 0; i < 16; i++) {
        const int r = wid + 8 * i;
        const int gr = row0 + r;
        float4 v = make_float4(0.f, 0.f, 0.f, 0.f);
        if (gr < NN) v = ((const float4*)(x + (size_t)gr * DD))[lane];
        float s = v.x + v.y + v.z + v.w;
        float q = v.x * v.x + v.y * v.y + v.z * v.z + v.w * v.w;
#pragma unroll
        for (int o = 16; o >= 1; o >>= 1) {
            s += __shfl_xor_sync(0xffffffffu, s, o);
            q += __shfl_xor_sync(0xffffffffu, q, o);
        }
        const float m = s * (1.f / 128.f);
        const float var = q * (1.f / 128.f) - m * m;
        const float rstd = rsqrtf(var + 1e-5f);
        float4 o4;
        o4.x = (v.x - m) * rstd * gv.x + bv.x;
        o4.y = (v.y - m) * rstd * gv.y + bv.y;
        o4.z = (v.z - m) * rstd * gv.z + bv.z;
        o4.w = (v.w - m) * rstd * gv.w + bv.w;
        if (gr < NN) {
            ((float4*)(g_xt + (size_t)gr * DD))[lane] = o4;
        } else {
            o4 = make_float4(0.f, 0.f, 0.f, 0.f);
        }
        As[(4 * lane + 0) * 132 + r] = o4.x;
        As[(4 * lane + 1) * 132 + r] = o4.y;
        As[(4 * lane + 2) * 132 + r] = o4.z;
        As[(4 * lane + 3) * 132 + r] = o4.w;
    }
    __syncthreads();

    // GEMM phase
    const int tx = t & 15;
    const int ty = t >> 4;
    float acc[8][8];
#pragma unroll
    for (int a = 0; a < 8; a++)
#pragma unroll
        for (int b = 0; b < 8; b++) acc[a][b] = 0.f;

#pragma unroll 4
    for (int k = 0; k < 128; k++) {
        const float4 a0 = *(const float4*)&As[k * 132 + 4 * ty];
        const float4 a1 = *(const float4*)&As[k * 132 + 64 + 4 * ty];
        const float4 b0 = *(const float4*)&Ws[k * 128 + 4 * tx];
        const float4 b1v = *(const float4*)&Ws[k * 128 + 64 + 4 * tx];
        const float av[8] = {a0.x, a0.y, a0.z, a0.w, a1.x, a1.y, a1.z, a1.w};
        const float bw[8] = {b0.x, b0.y, b0.z, b0.w, b1v.x, b1v.y, b1v.z, b1v.w};
#pragma unroll
        for (int a = 0; a < 8; a++)
#pragma unroll
            for (int b = 0; b < 8; b++) acc[a][b] += av[a] * bw[b];
    }

    // Store h
#pragma unroll
    for (int a = 0; a < 8; a++) {
        const int rl = (a < 4) ? (4 * ty + a) : (64 + 4 * ty + (a - 4));
        const int gr = row0 + rl;
        if (gr < NN) {
            float4 c0 = make_float4(acc[a][0], acc[a][1], acc[a][2], acc[a][3]);
            float4 c1 = make_float4(acc[a][4], acc[a][5], acc[a][6], acc[a][7]);
            *(float4*)&g_h[(size_t)gr * DD + 4 * tx] = c0;
            *(float4*)&g_h[(size_t)gr * DD + 64 + 4 * tx] = c1;
        }
    }
}

// ---------------------------------------------------------------------------
// K2b: attention scores a_src[n,h] = <h[n,h,:], att_src[h,:]>, same for dst.
// One warp per node; lane l covers cols 4l..4l+3, head = l/8.
// ---------------------------------------------------------------------------
__global__ __launch_bounds__(256)
void k_att(const float* __restrict__ att_s, const float* __restrict__ att_d) {
    const int g = blockIdx.x * blockDim.x + threadIdx.x;
    const int n = g >> 5;
    if (n >= NN) return;
    const int l = g & 31;
    const int head = l >> 3;
    const int cg = l & 7;
    const float4 hv = ((const float4*)(g_h + (size_t)n * DD))[l];
    const float4 sv = __ldg(((const float4*)(att_s + head * CCH)) + cg);
    const float4 dv = __ldg(((const float4*)(att_d + head * CCH)) + cg);
    float ps = hv.x * sv.x + hv.y * sv.y + hv.z * sv.z + hv.w * sv.w;
    float pd = hv.x * dv.x + hv.y * dv.y + hv.z * dv.z + hv.w * dv.w;
#pragma unroll
    for (int o = 4; o >= 1; o >>= 1) {
        ps += __shfl_down_sync(0xffffffffu, ps, o, 8);
        pd += __shfl_down_sync(0xffffffffu, pd, o, 8);
    }
    if (cg == 0) {
        g_asrc[n * HHEADS + head] = ps;
        g_adst[n * HHEADS + head] = pd;
    }
}

// ---------------------------------------------------------------------------
// K3: fused edge pass. One warp per edge (incl. self-loops e >= EE).
// w_h = exp(leaky_relu(a_src[s,h] + a_dst[d,h]))  (shift-free softmax)
// asum[d,h] += w_h ; agg[d,:] += w_head(c) * h[s,:]
// ---------------------------------------------------------------------------
__global__ __launch_bounds__(256)
void k_edge(const int* __restrict__ ei) {
    const int g = blockIdx.x * blockDim.x + threadIdx.x;
    const int e = g >> 5;
    if (e >= EE + NN) return;
    const int l = g & 31;
    int s, d;
    if (e < EE) {
        s = __ldg(ei + e);
        d = __ldg(ei + EE + e);
    } else {
        s = d = e - EE;
    }
    float w = 0.f;
    if (l < 4) {
        float a = g_asrc[s * HHEADS + l] + g_adst[d * HHEADS + l];
        a = (a > 0.f) ? a : 0.2f * a;
        w = __expf(a);
        atomicAdd(&g_asum[d * HHEADS + l], w);
    }
    const float wh = __shfl_sync(0xffffffffu, w, l >> 3);
    float4 hv = ((const float4*)(g_h + (size_t)s * DD))[l];
    hv.x *= wh; hv.y *= wh; hv.z *= wh; hv.w *= wh;
    red_add_f4(g_agg + (size_t)d * DD + 4 * l, hv);
}

// ---------------------------------------------------------------------------
// K4: epilogue. out = LN2( xt + agg/(asum+eps) + bias ). One warp per node.
// ---------------------------------------------------------------------------
__global__ __launch_bounds__(256)
void k_out(const float* __restrict__ bias, const float* __restrict__ g2,
           const float* __restrict__ b2, float* __restrict__ out) {
    const int g = blockIdx.x * blockDim.x + threadIdx.x;
    const int n = g >> 5;
    if (n >= NN) return;
    const int l = g & 31;
    const int head = l >> 3;
    const float4 xv = ((const float4*)(g_xt + (size_t)n * DD))[l];
    const float4 av = ((const float4*)(g_agg + (size_t)n * DD))[l];
    const float inv = 1.f / (g_asum[n * HHEADS + head] + 1e-16f);
    const float4 bv = __ldg(((const float4*)bias) + l);
    float4 v;
    v.x = xv.x + av.x * inv + bv.x;
    v.y = xv.y + av.y * inv + bv.y;
    v.z = xv.z + av.z * inv + bv.z;
    v.w = xv.w + av.w * inv + bv.w;
    float ssum = v.x + v.y + v.z + v.w;
    float q = v.x * v.x + v.y * v.y + v.z * v.z + v.w * v.w;
#pragma unroll
    for (int o = 16; o >= 1; o >>= 1) {
        ssum += __shfl_xor_sync(0xffffffffu, ssum, o);
        q += __shfl_xor_sync(0xffffffffu, q, o);
    }
    const float m = ssum * (1.f / 128.f);
    const float var = q * (1.f / 128.f) - m * m;
    const float rstd = rsqrtf(var + 1e-5f);
    const float4 gv = __ldg(((const float4*)g2) + l);
    const float4 b2v = __ldg(((const float4*)b2) + l);
    float4 o4;
    o4.x = (v.x - m) * rstd * gv.x + b2v.x;
    o4.y = (v.y - m) * rstd * gv.y + b2v.y;
    o4.z = (v.z - m) * rstd * gv.z + b2v.z;
    o4.w = (v.w - m) * rstd * gv.w + b2v.w;
    ((float4*)(out + (size_t)n * DD))[l] = o4;
}

// ---------------------------------------------------------------------------
extern "C" void kernel_launch(void* const* d_in, const int* in_sizes, int n_in,
                              void* d_out, int out_size) {
    const float* x     = (const float*)d_in[0];
    const int*   ei    = (const int*)d_in[1];
    // d_in[2] edge_attr, d_in[3] timestamps: unused by reference
    const float* Wg    = (const float*)d_in[4];
    const float* att_s = (const float*)d_in[5];
    const float* att_d = (const float*)d_in[6];
    const float* bias  = (const float*)d_in[7];
    const float* g1    = (const float*)d_in[8];
    const float* b1    = (const float*)d_in[9];
    const float* g2    = (const float*)d_in[10];
    const float* b2    = (const float*)d_in[11];
    float* out = (float*)d_out;

    void *p_asum = nullptr, *p_agg = nullptr;
    cudaGetSymbolAddress(&p_asum, g_asum);
    cudaGetSymbolAddress(&p_agg, g_agg);
    cudaMemsetAsync(p_asum, 0, (size_t)NN * HHEADS * sizeof(float), 0);
    cudaMemsetAsync(p_agg, 0, (size_t)NN * DD * sizeof(float), 0);

    const int smem_bytes = (128 * 132 + 128 * 128) * (int)sizeof(float);
    cudaFuncSetAttribute(k_ln_gemm, cudaFuncAttributeMaxDynamicSharedMemorySize, smem_bytes);

    k_ln_gemm<<<(NN + 127) / 128, 256, smem_bytes>>>(x, Wg, g1, b1);
    k_att<<<(NN * 32 + 255) / 256, 256>>>(att_s, att_d);
    k_edge<<<((EE + NN) * 32 + 255) / 256, 256>>>(ei);
    k_out<<<(NN * 32 + 255) / 256, 256>>>(bias, g2, b2, out);
}